// round 6
// baseline (speedup 1.0000x reference)
#include <cuda_runtime.h>
#include <math.h>

// ---------------------------------------------------------------------------
// SinkhornLoss: m=8, n=2048, d=3, eps=1e-3, 50 iters, early-stop flag.
// chain(i,k) = 2c*x_i.y_k + qb_k, qb_k = c*pot_k - c*||col_k||^2, c=log2e/eps.
// Columns stored DUPLICATED: {c0,c0,c1,c1,c2,c2,qb,qb} (32B) so two LDG.128
// directly give the four broadcast f32x2 operands for FFMA2 (no MOV packing).
// Rows processed in f32x2 pairs. qb refreshed by the previous half's finalize.
// ---------------------------------------------------------------------------

#define MB     8
#define NB     2048
#define EPSF   1e-3f
#define THRESH 1e-3f
#define NITERS 50
#define CSC    1442.6950408889634f      // log2(e)/eps
#define INVC   6.931471805599453e-4f    // 1/CSC = eps*ln2

#define ROWS   8                         // rows per block (4 f32x2 pairs)
#define PAIRS  (ROWS / 2)
#define WPB    2                         // warps per block (column split)
#define THREADS (WPB * 32)
#define CPW    (NB / WPB)                // 1024 columns per warp
#define TPW    (CPW / 32)                // 32 tile iters per warp
#define RGPB   (NB / ROWS)               // 256 row-groups per batch
#define GRID_HALF (MB * RGPB)            // 2048 blocks

typedef unsigned long long u64;

// Duplicated column record: two ulonglong2 loads -> broadcast f32x2 operands
struct __align__(32) Dup {
    float4 A;   // {c0, c0, c1, c1}
    float4 B;   // {c2, c2, qb, qb}
};

// Scratch (allocation-free rule: __device__ globals)
__device__ Dup      g_dx[MB * NB];  // x-side duplicated columns (qb = c*u - c*||x||^2)
__device__ Dup      g_dy[MB * NB];  // y-side duplicated columns (qb = c*v - c*||y||^2)
__device__ float4   g_cx[MB * NB];  // {x0,x1,x2, c*u - c*||x||^2} row-side reads + k_loss
__device__ float4   g_cy[MB * NB];  // {y0,y1,y2, c*v - c*||y||^2}
__device__ float    g_n2x[MB * NB]; // c*||x||^2 (exact)
__device__ float    g_n2y[MB * NB]; // c*||y||^2
__device__ float    g_u[MB * NB];
__device__ float    g_v[MB * NB];
__device__ float    g_la[MB * NB];
__device__ float    g_lb[MB * NB];
__device__ unsigned g_err[NITERS];  // per-iter max(err_u, err_v), float bits
__device__ int      g_done;         // sticky convergence flag

__device__ __forceinline__ float ex2f(float x) {
    float r; asm("ex2.approx.ftz.f32 %0, %1;" : "=f"(r) : "f"(x)); return r;
}
__device__ __forceinline__ u64 pack2(float lo, float hi) {
    u64 r; asm("mov.b64 %0, {%1, %2};" : "=l"(r) : "f"(lo), "f"(hi)); return r;
}
__device__ __forceinline__ float lo2(u64 p) {
    float l, h; asm("mov.b64 {%0, %1}, %2;" : "=f"(l), "=f"(h) : "l"(p)); return l;
}
__device__ __forceinline__ float hi2(u64 p) {
    float l, h; asm("mov.b64 {%0, %1}, %2;" : "=f"(l), "=f"(h) : "l"(p)); return h;
}
__device__ __forceinline__ u64 fma2(u64 a, u64 b, u64 c) {
    u64 d; asm("fma.rn.f32x2 %0, %1, %2, %3;" : "=l"(d) : "l"(a), "l"(b), "l"(c)); return d;
}
__device__ __forceinline__ u64 add2(u64 a, u64 b) {
    u64 d; asm("add.rn.f32x2 %0, %1, %2;" : "=l"(d) : "l"(a), "l"(b)); return d;
}

// ---------------------------------------------------------------------------
__global__ void k_init(const float* __restrict__ px, const float* __restrict__ py,
                       const float* __restrict__ a, const float* __restrict__ b,
                       float* __restrict__ out) {
    int i = blockIdx.x * blockDim.x + threadIdx.x;
    if (i < MB * NB) {
        float x0 = px[3 * i], x1 = px[3 * i + 1], x2 = px[3 * i + 2];
        float n2x = CSC * (x0 * x0 + x1 * x1 + x2 * x2);
        g_cx[i] = make_float4(x0, x1, x2, -n2x);            // u = 0
        g_dx[i].A = make_float4(x0, x0, x1, x1);
        g_dx[i].B = make_float4(x2, x2, -n2x, -n2x);
        g_n2x[i] = n2x;
        float y0 = py[3 * i], y1 = py[3 * i + 1], y2 = py[3 * i + 2];
        float n2y = CSC * (y0 * y0 + y1 * y1 + y2 * y2);
        g_cy[i] = make_float4(y0, y1, y2, -n2y);            // v = 0
        g_dy[i].A = make_float4(y0, y0, y1, y1);
        g_dy[i].B = make_float4(y2, y2, -n2y, -n2y);
        g_n2y[i] = n2y;
        g_u[i] = 0.0f;
        g_v[i] = 0.0f;
        g_la[i] = logf(a[i]);
        g_lb[i] = logf(b[i]);
    }
    if (i < NITERS) g_err[i] = 0u;
    if (i == 0)     g_done = 0;
    if (i < MB)     out[i] = 0.0f;
}

// ---------------------------------------------------------------------------
// One half Sinkhorn update. SIDE=0 updates u (rows=x, cols=y+v);
//                           SIDE=1 updates v (rows=y, cols=x+u).
template <int SIDE>
__global__ void __launch_bounds__(THREADS, 16) k_half(int iter) {
    __shared__ float s_mx[WPB][ROWS];
    __shared__ float s_sm[WPB][ROWS];
    __shared__ int s_done;
    if (threadIdx.x == 0) {
        int d = g_done;
        if (!d && iter > 0 && __uint_as_float(g_err[iter - 1]) < THRESH) {
            d = 1;
            g_done = 1;          // sticky, monotone: benign race
        }
        s_done = d;
    }
    __syncthreads();
    if (s_done) return;          // frozen once converged (reference semantics)

    const int warp  = threadIdx.x >> 5;
    const int lane  = threadIdx.x & 31;
    const int batch = blockIdx.x / RGPB;
    const int row0  = (blockIdx.x % RGPB) * ROWS;
    const int base  = batch * NB;

    const float4* __restrict__ rp  = SIDE ? g_cy : g_cx;     // row-side coords
    const u64*    __restrict__ cp  = SIDE ? (const u64*)g_dx : (const u64*)g_dy;
    float4*                    rw  = SIDE ? g_cy : g_cx;     // row-side AoS qb write
    Dup*                       dw  = SIDE ? g_dy : g_dx;     // row-side dup qb write
    const float*  __restrict__ n2  = SIDE ? g_n2y : g_n2x;   // c*||row||^2
    float*                     upd = SIDE ? g_v : g_u;       // potential being updated
    const float*  __restrict__ rl  = SIDE ? g_lb : g_la;     // row-side log marginal

    // Row-pair packed coordinates, pre-scaled by 2c
    u64 cx2[PAIRS], cy2[PAIRS], cz2[PAIRS];
    float mxs[ROWS];
#pragma unroll
    for (int p = 0; p < PAIRS; p++) {
        float4 R0 = rp[base + row0 + 2 * p];
        float4 R1 = rp[base + row0 + 2 * p + 1];
        cx2[p] = pack2(R0.x * (2.0f * CSC), R1.x * (2.0f * CSC));
        cy2[p] = pack2(R0.y * (2.0f * CSC), R1.y * (2.0f * CSC));
        cz2[p] = pack2(R0.z * (2.0f * CSC), R1.z * (2.0f * CSC));
    }
#pragma unroll
    for (int j = 0; j < ROWS; j++) mxs[j] = -3.4e38f;
    const u64* cpw = cp + (u64)(base + warp * CPW + lane) * 4;   // 4 u64 per column

    // ---- Pass 1: row max of chain = 2c*row.col + qb
#pragma unroll 2
    for (int t = 0; t < TPW; t++) {
        const u64* c4 = cpw + (u64)t * 32 * 4;
        ulonglong2 ca = *(const ulonglong2*)(c4);       // {(c0,c0),(c1,c1)}
        ulonglong2 cb = *(const ulonglong2*)(c4 + 2);   // {(c2,c2),(qb,qb)}
#pragma unroll
        for (int p = 0; p < PAIRS; p++) {
            u64 s2 = fma2(cx2[p], ca.x, fma2(cy2[p], ca.y, fma2(cz2[p], cb.x, cb.y)));
            mxs[2 * p]     = fmaxf(mxs[2 * p],     lo2(s2));
            mxs[2 * p + 1] = fmaxf(mxs[2 * p + 1], hi2(s2));
        }
    }
#pragma unroll
    for (int j = 0; j < ROWS; j++) {
#pragma unroll
        for (int o = 16; o; o >>= 1)
            mxs[j] = fmaxf(mxs[j], __shfl_xor_sync(0xffffffffu, mxs[j], o));
    }
    if (lane == 0) {
#pragma unroll
        for (int j = 0; j < ROWS; j++) s_mx[warp][j] = mxs[j];
    }
    __syncthreads();
    u64 nmx2[PAIRS];
#pragma unroll
    for (int p = 0; p < PAIRS; p++) {
        float m0 = fmaxf(s_mx[0][2 * p],     s_mx[1][2 * p]);
        float m1 = fmaxf(s_mx[0][2 * p + 1], s_mx[1][2 * p + 1]);
        nmx2[p] = pack2(-m0, -m1);
    }

    // ---- Pass 2: row sum of ex2(chain - mx)  (same chain bits => arg <= 0)
    float sm[ROWS];
#pragma unroll
    for (int j = 0; j < ROWS; j++) sm[j] = 0.0f;

#pragma unroll 2
    for (int t = 0; t < TPW; t++) {
        const u64* c4 = cpw + (u64)t * 32 * 4;
        ulonglong2 ca = *(const ulonglong2*)(c4);
        ulonglong2 cb = *(const ulonglong2*)(c4 + 2);
#pragma unroll
        for (int p = 0; p < PAIRS; p++) {
            u64 s2 = fma2(cx2[p], ca.x, fma2(cy2[p], ca.y, fma2(cz2[p], cb.x, cb.y)));
            u64 a2 = add2(s2, nmx2[p]);
            sm[2 * p]     += ex2f(lo2(a2));
            sm[2 * p + 1] += ex2f(hi2(a2));
        }
    }
#pragma unroll
    for (int j = 0; j < ROWS; j++) {
#pragma unroll
        for (int o = 16; o; o >>= 1)
            sm[j] += __shfl_xor_sync(0xffffffffu, sm[j], o);
    }
    if (lane == 0) {
#pragma unroll
        for (int j = 0; j < ROWS; j++) s_sm[warp][j] = sm[j];
    }
    __syncthreads();

    // ---- Finalize: warp 0, lanes 0..7 each own one row
    if (warp == 0 && lane < ROWS) {
        int r = base + row0 + lane;
        float smv = s_sm[0][lane] + s_sm[1][lane];
        float mxc = fmaxf(s_mx[0][lane], s_mx[1][lane]);
        float n2r = n2[r];                           // c*||row||^2 (exact)
        float mx_row = (mxc - n2r) * INVC;           // true max of (pot - M)
        float nv = EPSF * rl[r] - mx_row - EPSF * __logf(smv);
        float ov = upd[r];
        upd[r] = nv;
        // refresh this row's column-side qb: c*pot_new - c*||row||^2
        float qb = fmaf(CSC, nv, -n2r);
        ((float*)(rw + r))[3] = qb;                  // AoS copy (row reads + k_loss)
        ((float2*)&dw[r].B)[1] = make_float2(qb, qb);// duplicated copy (hot loop)
        float e = fabsf(nv - ov);
#pragma unroll
        for (int o = 4; o; o >>= 1)
            e = fmaxf(e, __shfl_xor_sync(0x000000ffu, e, o));
        if (lane == 0)
            atomicMax(&g_err[iter], __float_as_uint(e));  // e>=0: uint order==float order
    }
}

// ---------------------------------------------------------------------------
// loss[b] = sum_{i,k} M * exp((u_i + v_k - M)/eps)
__global__ void __launch_bounds__(THREADS, 16) k_loss(float* __restrict__ out) {
    const int warp  = threadIdx.x >> 5;
    const int lane  = threadIdx.x & 31;
    const int batch = blockIdx.x / RGPB;
    const int row0  = (blockIdx.x % RGPB) * ROWS;
    const int base  = batch * NB;

    float cx[ROWS], cy[ROWS], cz[ROWS], aj[ROWS], U[ROWS];
#pragma unroll
    for (int j = 0; j < ROWS; j++) {
        float4 R = g_cx[base + row0 + j];            // {x, c*u - c*x2}
        cx[j] = R.x * (2.0f * CSC);
        cy[j] = R.y * (2.0f * CSC);
        cz[j] = R.z * (2.0f * CSC);
        aj[j] = R.w;
        U[j]  = g_u[base + row0 + j];
    }
    const int kbeg = base + warp * CPW + lane;

    float tot = 0.0f;
#pragma unroll 2
    for (int t = 0; t < TPW; t++) {
        int k = kbeg + t * 32;
        float4 C = g_cy[k];                          // {y, c*v - c*y2}
        float vk = g_v[k];
#pragma unroll
        for (int j = 0; j < ROWS; j++) {
            // carg = c*(u + v - M)
            float carg = fmaf(cx[j], C.x, fmaf(cy[j], C.y, fmaf(cz[j], C.z, C.w + aj[j])));
            float e  = ex2f(carg);
            float uv = U[j] + vk;
            float Mv = fmaf(carg, -INVC, uv);        // = M (unclamped)
            tot = fmaf(Mv, e, tot);
        }
    }
#pragma unroll
    for (int o = 16; o; o >>= 1)
        tot += __shfl_xor_sync(0xffffffffu, tot, o);
    if (lane == 0) atomicAdd(&out[batch], tot);
}

// ---------------------------------------------------------------------------
extern "C" void kernel_launch(void* const* d_in, const int* in_sizes, int n_in,
                              void* d_out, int out_size) {
    (void)in_sizes; (void)n_in; (void)out_size;
    const float* px = (const float*)d_in[0];   // predicted [8,2048,3]
    const float* py = (const float*)d_in[1];   // expected  [8,2048,3]
    const float* a  = (const float*)d_in[2];   // [8,2048]
    const float* b  = (const float*)d_in[3];   // [8,2048]
    float* out = (float*)d_out;                // [8]

    k_init<<<(MB * NB + 255) / 256, 256>>>(px, py, a, b, out);
    for (int t = 0; t < NITERS; t++) {
        k_half<0><<<GRID_HALF, THREADS>>>(t);
        k_half<1><<<GRID_HALF, THREADS>>>(t);
    }
    k_loss<<<GRID_HALF, THREADS>>>(out);
}

// round 7
// speedup vs baseline: 1.0248x; 1.0248x over previous
#include <cuda_runtime.h>
#include <math.h>

// ---------------------------------------------------------------------------
// SinkhornLoss: m=8, n=2048, d=3, eps=1e-3, 50 iters, early-stop flag.
// chain(i,k) = 2c*x_i.y_k + qb_k, qb_k = c*pot_k - c*||col_k||^2, c=log2e/eps,
// with qb maintained in the column float4's .w by the previous half's finalize.
// Rows in f32x2 pairs (FFMA2). ROWS=4 per block -> 4096 blocks / 8192 warps
// (occupancy was grid-limited at ROWS=8). AoS float4 columns (dup layout of
// R5 regressed: doubled L2 traffic).
// ---------------------------------------------------------------------------

#define MB     8
#define NB     2048
#define EPSF   1e-3f
#define THRESH 1e-3f
#define NITERS 50
#define CSC    1442.6950408889634f      // log2(e)/eps
#define INVC   6.931471805599453e-4f    // 1/CSC = eps*ln2

#define ROWS   4                         // rows per block (2 f32x2 pairs)
#define PAIRS  (ROWS / 2)
#define WPB    2                         // warps per block (column split)
#define THREADS (WPB * 32)
#define CPW    (NB / WPB)                // 1024 columns per warp
#define TPW    (CPW / 32)                // 32 tile iters per warp
#define RGPB   (NB / ROWS)               // 512 row-groups per batch
#define GRID_HALF (MB * RGPB)            // 4096 blocks

typedef unsigned long long u64;

// Scratch (allocation-free rule: __device__ globals)
__device__ float4   g_cx[MB * NB];  // {x0,x1,x2, c*u - c*||x||^2}
__device__ float4   g_cy[MB * NB];  // {y0,y1,y2, c*v - c*||y||^2}
__device__ float    g_n2x[MB * NB]; // c*||x||^2 (exact, no drift)
__device__ float    g_n2y[MB * NB]; // c*||y||^2
__device__ float    g_u[MB * NB];
__device__ float    g_v[MB * NB];
__device__ float    g_la[MB * NB];
__device__ float    g_lb[MB * NB];
__device__ unsigned g_err[NITERS];  // per-iter max(err_u, err_v), float bits
__device__ int      g_done;         // sticky convergence flag

__device__ __forceinline__ float ex2f(float x) {
    float r; asm("ex2.approx.ftz.f32 %0, %1;" : "=f"(r) : "f"(x)); return r;
}
__device__ __forceinline__ u64 pack2(float lo, float hi) {
    u64 r; asm("mov.b64 %0, {%1, %2};" : "=l"(r) : "f"(lo), "f"(hi)); return r;
}
__device__ __forceinline__ float lo2(u64 p) {
    float l, h; asm("mov.b64 {%0, %1}, %2;" : "=f"(l), "=f"(h) : "l"(p)); return l;
}
__device__ __forceinline__ float hi2(u64 p) {
    float l, h; asm("mov.b64 {%0, %1}, %2;" : "=f"(l), "=f"(h) : "l"(p)); return h;
}
__device__ __forceinline__ u64 fma2(u64 a, u64 b, u64 c) {
    u64 d; asm("fma.rn.f32x2 %0, %1, %2, %3;" : "=l"(d) : "l"(a), "l"(b), "l"(c)); return d;
}
__device__ __forceinline__ u64 add2(u64 a, u64 b) {
    u64 d; asm("add.rn.f32x2 %0, %1, %2;" : "=l"(d) : "l"(a), "l"(b)); return d;
}

// ---------------------------------------------------------------------------
__global__ void k_init(const float* __restrict__ px, const float* __restrict__ py,
                       const float* __restrict__ a, const float* __restrict__ b,
                       float* __restrict__ out) {
    int i = blockIdx.x * blockDim.x + threadIdx.x;
    if (i < MB * NB) {
        float x0 = px[3 * i], x1 = px[3 * i + 1], x2 = px[3 * i + 2];
        float n2x = CSC * (x0 * x0 + x1 * x1 + x2 * x2);
        g_cx[i] = make_float4(x0, x1, x2, -n2x);     // u = 0
        g_n2x[i] = n2x;
        float y0 = py[3 * i], y1 = py[3 * i + 1], y2 = py[3 * i + 2];
        float n2y = CSC * (y0 * y0 + y1 * y1 + y2 * y2);
        g_cy[i] = make_float4(y0, y1, y2, -n2y);     // v = 0
        g_n2y[i] = n2y;
        g_u[i] = 0.0f;
        g_v[i] = 0.0f;
        g_la[i] = logf(a[i]);
        g_lb[i] = logf(b[i]);
    }
    if (i < NITERS) g_err[i] = 0u;
    if (i == 0)     g_done = 0;
    if (i < MB)     out[i] = 0.0f;
}

// ---------------------------------------------------------------------------
// One half Sinkhorn update. SIDE=0 updates u (rows=x, cols=y+v);
//                           SIDE=1 updates v (rows=y, cols=x+u).
template <int SIDE>
__global__ void __launch_bounds__(THREADS, 24) k_half(int iter) {
    __shared__ float s_mx[WPB][ROWS];
    __shared__ float s_sm[WPB][ROWS];
    __shared__ int s_done;
    if (threadIdx.x == 0) {
        int d = g_done;
        if (!d && iter > 0 && __uint_as_float(g_err[iter - 1]) < THRESH) {
            d = 1;
            g_done = 1;          // sticky, monotone: benign race
        }
        s_done = d;
    }
    __syncthreads();
    if (s_done) return;          // frozen once converged (reference semantics)

    const int warp  = threadIdx.x >> 5;
    const int lane  = threadIdx.x & 31;
    const int batch = blockIdx.x / RGPB;
    const int row0  = (blockIdx.x % RGPB) * ROWS;
    const int base  = batch * NB;

    const float4* __restrict__ rp  = SIDE ? g_cy : g_cx;   // row-side coords
    const float4* __restrict__ cp  = SIDE ? g_cx : g_cy;   // col-side {coords, qb}
    float4*                    rw  = SIDE ? g_cy : g_cx;   // row-side (finalize .w write)
    const float*  __restrict__ n2  = SIDE ? g_n2y : g_n2x; // c*||row||^2
    float*                     upd = SIDE ? g_v : g_u;     // potential being updated
    const float*  __restrict__ rl  = SIDE ? g_lb : g_la;   // row-side log marginal

    // Row-pair packed coordinates, pre-scaled by 2c
    u64 cx2[PAIRS], cy2[PAIRS], cz2[PAIRS];
    float mxs[ROWS];
#pragma unroll
    for (int p = 0; p < PAIRS; p++) {
        float4 R0 = rp[base + row0 + 2 * p];
        float4 R1 = rp[base + row0 + 2 * p + 1];
        cx2[p] = pack2(R0.x * (2.0f * CSC), R1.x * (2.0f * CSC));
        cy2[p] = pack2(R0.y * (2.0f * CSC), R1.y * (2.0f * CSC));
        cz2[p] = pack2(R0.z * (2.0f * CSC), R1.z * (2.0f * CSC));
    }
#pragma unroll
    for (int j = 0; j < ROWS; j++) mxs[j] = -3.4e38f;
    const int kbeg = base + warp * CPW + lane;

    // ---- Pass 1: row max of chain = 2c*row.col + qb
#pragma unroll 4
    for (int t = 0; t < TPW; t++) {
        int k = kbeg + t * 32;
        float4 C = cp[k];                        // {c0,c1,c2, qb}
        u64 Cx = pack2(C.x, C.x), Cy = pack2(C.y, C.y), Cz = pack2(C.z, C.z);
        u64 Q  = pack2(C.w, C.w);
#pragma unroll
        for (int p = 0; p < PAIRS; p++) {
            u64 s2 = fma2(cx2[p], Cx, fma2(cy2[p], Cy, fma2(cz2[p], Cz, Q)));
            mxs[2 * p]     = fmaxf(mxs[2 * p],     lo2(s2));
            mxs[2 * p + 1] = fmaxf(mxs[2 * p + 1], hi2(s2));
        }
    }
#pragma unroll
    for (int j = 0; j < ROWS; j++) {
#pragma unroll
        for (int o = 16; o; o >>= 1)
            mxs[j] = fmaxf(mxs[j], __shfl_xor_sync(0xffffffffu, mxs[j], o));
    }
    if (lane == 0) {
#pragma unroll
        for (int j = 0; j < ROWS; j++) s_mx[warp][j] = mxs[j];
    }
    __syncthreads();
    u64 nmx2[PAIRS];
#pragma unroll
    for (int p = 0; p < PAIRS; p++) {
        float m0 = fmaxf(s_mx[0][2 * p],     s_mx[1][2 * p]);
        float m1 = fmaxf(s_mx[0][2 * p + 1], s_mx[1][2 * p + 1]);
        nmx2[p] = pack2(-m0, -m1);
    }

    // ---- Pass 2: row sum of ex2(chain - mx)  (same chain bits => arg <= 0)
    float sm[ROWS];
#pragma unroll
    for (int j = 0; j < ROWS; j++) sm[j] = 0.0f;

#pragma unroll 4
    for (int t = 0; t < TPW; t++) {
        int k = kbeg + t * 32;
        float4 C = cp[k];
        u64 Cx = pack2(C.x, C.x), Cy = pack2(C.y, C.y), Cz = pack2(C.z, C.z);
        u64 Q  = pack2(C.w, C.w);
#pragma unroll
        for (int p = 0; p < PAIRS; p++) {
            u64 s2 = fma2(cx2[p], Cx, fma2(cy2[p], Cy, fma2(cz2[p], Cz, Q)));
            u64 a2 = add2(s2, nmx2[p]);
            sm[2 * p]     += ex2f(lo2(a2));
            sm[2 * p + 1] += ex2f(hi2(a2));
        }
    }
#pragma unroll
    for (int j = 0; j < ROWS; j++) {
#pragma unroll
        for (int o = 16; o; o >>= 1)
            sm[j] += __shfl_xor_sync(0xffffffffu, sm[j], o);
    }
    if (lane == 0) {
#pragma unroll
        for (int j = 0; j < ROWS; j++) s_sm[warp][j] = sm[j];
    }
    __syncthreads();

    // ---- Finalize: warp 0, lanes 0..3 each own one row
    if (warp == 0 && lane < ROWS) {
        int r = base + row0 + lane;
        float smv = s_sm[0][lane] + s_sm[1][lane];
        float mxc = fmaxf(s_mx[0][lane], s_mx[1][lane]);
        float n2r = n2[r];                           // c*||row||^2 (exact)
        float mx_row = (mxc - n2r) * INVC;           // true max of (pot - M)
        float nv = EPSF * rl[r] - mx_row - EPSF * __logf(smv);
        float ov = upd[r];
        upd[r] = nv;
        // refresh this row's column-side qb: c*pot_new - c*||row||^2
        ((float*)(rw + r))[3] = fmaf(CSC, nv, -n2r);
        float e = fabsf(nv - ov);
#pragma unroll
        for (int o = 2; o; o >>= 1)
            e = fmaxf(e, __shfl_xor_sync(0x0000000fu, e, o));
        if (lane == 0)
            atomicMax(&g_err[iter], __float_as_uint(e));  // e>=0: uint order==float order
    }
}

// ---------------------------------------------------------------------------
// loss[b] = sum_{i,k} M * exp((u_i + v_k - M)/eps)
__global__ void __launch_bounds__(THREADS, 24) k_loss(float* __restrict__ out) {
    const int warp  = threadIdx.x >> 5;
    const int lane  = threadIdx.x & 31;
    const int batch = blockIdx.x / RGPB;
    const int row0  = (blockIdx.x % RGPB) * ROWS;
    const int base  = batch * NB;

    float cx[ROWS], cy[ROWS], cz[ROWS], aj[ROWS], U[ROWS];
#pragma unroll
    for (int j = 0; j < ROWS; j++) {
        float4 R = g_cx[base + row0 + j];            // {x, c*u - c*x2}
        cx[j] = R.x * (2.0f * CSC);
        cy[j] = R.y * (2.0f * CSC);
        cz[j] = R.z * (2.0f * CSC);
        aj[j] = R.w;
        U[j]  = g_u[base + row0 + j];
    }
    const int kbeg = base + warp * CPW + lane;

    float tot = 0.0f;
#pragma unroll 4
    for (int t = 0; t < TPW; t++) {
        int k = kbeg + t * 32;
        float4 C = g_cy[k];                          // {y, c*v - c*y2}
        float vk = g_v[k];
#pragma unroll
        for (int j = 0; j < ROWS; j++) {
            // carg = c*(u + v - M)
            float carg = fmaf(cx[j], C.x, fmaf(cy[j], C.y, fmaf(cz[j], C.z, C.w + aj[j])));
            float e  = ex2f(carg);
            float uv = U[j] + vk;
            float Mv = fmaf(carg, -INVC, uv);        // = M (unclamped)
            tot = fmaf(Mv, e, tot);
        }
    }
#pragma unroll
    for (int o = 16; o; o >>= 1)
        tot += __shfl_xor_sync(0xffffffffu, tot, o);
    if (lane == 0) atomicAdd(&out[batch], tot);
}

// ---------------------------------------------------------------------------
extern "C" void kernel_launch(void* const* d_in, const int* in_sizes, int n_in,
                              void* d_out, int out_size) {
    (void)in_sizes; (void)n_in; (void)out_size;
    const float* px = (const float*)d_in[0];   // predicted [8,2048,3]
    const float* py = (const float*)d_in[1];   // expected  [8,2048,3]
    const float* a  = (const float*)d_in[2];   // [8,2048]
    const float* b  = (const float*)d_in[3];   // [8,2048]
    float* out = (float*)d_out;                // [8]

    k_init<<<(MB * NB + 255) / 256, 256>>>(px, py, a, b, out);
    for (int t = 0; t < NITERS; t++) {
        k_half<0><<<GRID_HALF, THREADS>>>(t);
        k_half<1><<<GRID_HALF, THREADS>>>(t);
    }
    k_loss<<<GRID_HALF, THREADS>>>(out);
}